// round 1
// baseline (speedup 1.0000x reference)
#include <cuda_runtime.h>
#include <math.h>

#define BB 4
#define LL 4096
#define HIDN 1024
#define HH 16
#define DD 64
#define DMM 128
#define CSZ 64
#define NCH 64
#define MM (BB*LL)
#define EPSF 1e-6f

// ---------------- scratch (static device globals; no allocs allowed) ----------------
static __device__ float g_qkv [(size_t)3*MM*HIDN];        // raw q,k,v projections [3][M][1024]
static __device__ float g_proc[(size_t)3*BB*HH*LL*DD];    // processed q,k,v  [3][B*H][L][D]
static __device__ float g_gate[(size_t)3*BB*HH*LL];       // md, sd, lr       [3][B*H][L]

#define NPROC ((size_t)BB*HH*LL*DD)
#define NGATE ((size_t)BB*HH*LL)

__device__ __forceinline__ float sigmf(float x) {
    return __fdividef(1.0f, 1.0f + __expf(-x));
}

// ---------------- K1: qkv projection GEMM  C = X @ W^T ----------------
// BM=BN=64, BK=16, 256 threads, 4x4 per thread
__global__ void __launch_bounds__(256) k_qkv(
    const float* __restrict__ X,
    const float* __restrict__ Wq, const float* __restrict__ Wk, const float* __restrict__ Wv)
{
    __shared__ float As[16][68];
    __shared__ float Bs[16][68];
    const float* W = (blockIdx.z == 0) ? Wq : ((blockIdx.z == 1) ? Wk : Wv);
    float* C = g_qkv + (size_t)blockIdx.z * MM * HIDN;
    const int m0 = blockIdx.y * 64, n0 = blockIdx.x * 64;
    const int t = threadIdx.x;
    const int lr = t >> 2, lk = (t & 3) * 4;
    const int ty = t >> 4, tx = t & 15;
    float acc[4][4] = {};
    const float* Arow = X + (size_t)(m0 + lr) * HIDN + lk;
    const float* Brow = W + (size_t)(n0 + lr) * HIDN + lk;
    for (int k0 = 0; k0 < HIDN; k0 += 16) {
        float4 av = *(const float4*)(Arow + k0);
        float4 bv = *(const float4*)(Brow + k0);
        As[lk + 0][lr] = av.x; As[lk + 1][lr] = av.y; As[lk + 2][lr] = av.z; As[lk + 3][lr] = av.w;
        Bs[lk + 0][lr] = bv.x; Bs[lk + 1][lr] = bv.y; Bs[lk + 2][lr] = bv.z; Bs[lk + 3][lr] = bv.w;
        __syncthreads();
#pragma unroll
        for (int kk = 0; kk < 16; kk++) {
            float4 a = *(const float4*)&As[kk][ty * 4];
            float4 b = *(const float4*)&Bs[kk][tx * 4];
            float ar[4] = {a.x, a.y, a.z, a.w};
            float br[4] = {b.x, b.y, b.z, b.w};
#pragma unroll
            for (int i = 0; i < 4; i++)
#pragma unroll
                for (int j = 0; j < 4; j++) acc[i][j] += ar[i] * br[j];
        }
        __syncthreads();
    }
#pragma unroll
    for (int i = 0; i < 4; i++) {
        float4 o; o.x = acc[i][0]; o.y = acc[i][1]; o.z = acc[i][2]; o.w = acc[i][3];
        *(float4*)(C + (size_t)(m0 + ty * 4 + i) * HIDN + n0 + tx * 4) = o;
    }
}

// ---------------- K2: gate projections (N=48) + sigmoid transforms ----------------
// BM=64, BN=48, BK=16, 256 threads, 4x3 per thread
__global__ void __launch_bounds__(256) k_gate(
    const float* __restrict__ X,
    const float* __restrict__ mdw, const float* __restrict__ mdb,
    const float* __restrict__ sw,  const float* __restrict__ sb,
    const float* __restrict__ lw,  const float* __restrict__ lb)
{
    __shared__ float As[16][68];
    __shared__ float Bg[16][52];
    const int m0 = blockIdx.x * 64;
    const int t = threadIdx.x;
    const int lr = t >> 2, lk = (t & 3) * 4;
    const int ty = t >> 4, tx = t & 15;
    float acc[4][3] = {};
    const float* Arow = X + (size_t)(m0 + lr) * HIDN + lk;
    for (int k0 = 0; k0 < HIDN; k0 += 16) {
        float4 av = *(const float4*)(Arow + k0);
        As[lk + 0][lr] = av.x; As[lk + 1][lr] = av.y; As[lk + 2][lr] = av.z; As[lk + 3][lr] = av.w;
        if (t < 192) {
#pragma unroll
            for (int j = 0; j < 4; j++) {
                int idx = t * 4 + j;
                int n = idx >> 4, k = idx & 15;
                const float* wp = (n < 16) ? (mdw + (size_t)n * HIDN)
                                : (n < 32) ? (sw + (size_t)(n - 16) * HIDN)
                                           : (lw + (size_t)(n - 32) * HIDN);
                Bg[k][n] = wp[k0 + k];
            }
        }
        __syncthreads();
#pragma unroll
        for (int kk = 0; kk < 16; kk++) {
            float4 a = *(const float4*)&As[kk][ty * 4];
            float ar[4] = {a.x, a.y, a.z, a.w};
            float b0 = Bg[kk][tx * 3 + 0];
            float b1 = Bg[kk][tx * 3 + 1];
            float b2 = Bg[kk][tx * 3 + 2];
#pragma unroll
            for (int i = 0; i < 4; i++) {
                acc[i][0] += ar[i] * b0;
                acc[i][1] += ar[i] * b1;
                acc[i][2] += ar[i] * b2;
            }
        }
        __syncthreads();
    }
#pragma unroll
    for (int i = 0; i < 4; i++) {
#pragma unroll
        for (int j = 0; j < 3; j++) {
            int m = m0 + ty * 4 + i;
            int o = tx * 3 + j;
            float bias = (o < 16) ? mdb[o] : (o < 32) ? sb[o - 16] : lb[o - 32];
            float v = sigmf(acc[i][j] + bias);
            int bcur = m >> 12;           // m / L
            int l = m & (LL - 1);
            int g = o >> 4;
            int hh = o & 15;
            size_t gi = (size_t)g * NGATE + ((size_t)(bcur * HH + hh)) * LL + l;
            g_gate[gi] = (g == 0) ? (1.0f - v) : v;
        }
    }
}

// ---------------- K3: causal conv(K=4) + silu (+ rmsnorm for q,k) ----------------
// one block per (l, b, tensor z); 256 threads * 4 channels
__global__ void __launch_bounds__(256) k_conv(
    const float* __restrict__ cqw, const float* __restrict__ cqb,
    const float* __restrict__ ckw, const float* __restrict__ ckb,
    const float* __restrict__ cvw, const float* __restrict__ cvb,
    const float* __restrict__ qnw, const float* __restrict__ knw)
{
    const int z = blockIdx.z;
    const int b = blockIdx.y;
    const int l = blockIdx.x;
    const float* w    = (z == 0) ? cqw : (z == 1) ? ckw : cvw;
    const float* bias = (z == 0) ? cqb : (z == 1) ? ckb : cvb;
    const float* src = g_qkv + (size_t)z * MM * HIDN + (size_t)b * LL * HIDN;
    __shared__ float hs[16];
    const int t = threadIdx.x;
    if (t < 16) hs[t] = 0.0f;
    __syncthreads();
    const int c0 = t * 4;
    float y[4];
#pragma unroll
    for (int j = 0; j < 4; j++) y[j] = bias[c0 + j];
#pragma unroll
    for (int j = 0; j < 4; j++) {   // j = how far back in time
        int ls = l - j;
        if (ls >= 0) {
            float4 x = *(const float4*)(src + (size_t)ls * HIDN + c0);
            int k = 3 - j;
            y[0] += w[(c0 + 0) * 4 + k] * x.x;
            y[1] += w[(c0 + 1) * 4 + k] * x.y;
            y[2] += w[(c0 + 2) * 4 + k] * x.z;
            y[3] += w[(c0 + 3) * 4 + k] * x.w;
        }
    }
#pragma unroll
    for (int j = 0; j < 4; j++) y[j] = y[j] * sigmf(y[j]);
    const int head = c0 >> 6;
    const int d0 = c0 & 63;
    float* dst = g_proc + (size_t)z * NPROC + (((size_t)(b * HH + head)) * LL + l) * DD + d0;
    if (z < 2) {
        float ss = y[0] * y[0] + y[1] * y[1] + y[2] * y[2] + y[3] * y[3];
        atomicAdd(&hs[head], ss);
        __syncthreads();
        float scale = rsqrtf(hs[head] * (1.0f / 64.0f) + EPSF);
        const float* nw = (z == 0) ? qnw : knw;
#pragma unroll
        for (int j = 0; j < 4; j++) y[j] *= scale * nw[d0 + j];
    }
    float4 o; o.x = y[0]; o.y = y[1]; o.z = y[2]; o.w = y[3];
    *(float4*)dst = o;
}

// ---------------- K4: chunked recurrent scan, one block per (b,h) ----------------
// smem layout offsets (floats)
#define SW1_OFF 0
#define SW1_SZ  (64*132)
#define SW2_OFF (SW1_OFF+SW1_SZ)
#define SW2_SZ  (128*68)
#define SZ1_OFF (SW2_OFF+SW2_SZ)
#define SBUF_SZ (64*132)
#define SX1_OFF (SZ1_OFF+SBUF_SZ)
#define SSG_OFF (SX1_OFF+SBUF_SZ)
#define SKT_OFF (SSG_OFF+SBUF_SZ)
#define SKT_SZ  (64*68)
#define SGT_OFF (SKT_OFF+SKT_SZ)
#define SVC_OFF (SGT_OFF+SKT_SZ)
#define SVEC_OFF (SVC_OFF+SKT_SZ)
#define SMEM_FLOATS (SVEC_OFF + 577)
#define SMEM_BYTES (SMEM_FLOATS*4)

__global__ void __launch_bounds__(256, 1) k_scan(
    const float* __restrict__ W1g, const float* __restrict__ W2g, float* __restrict__ out)
{
    extern __shared__ float sm[];
    float* sW1 = sm + SW1_OFF;   // [64][132]  W1[d][c]
    float* sW2 = sm + SW2_OFF;   // [128][68]  W2[c][d]
    float* sZ1 = sm + SZ1_OFF;   // [64][132]  Z1 (later silu(Zq))
    float* sX1 = sm + SX1_OFF;   // [64][132]  X1 (later g_Z1)
    float* sSG = sm + SSG_OFF;   // [64][132]  sigmoid(Z1)
    float* sKT = sm + SKT_OFF;   // [64][68]   kc^T[d][i] (later qc^T)
    float* sGT = sm + SGT_OFF;   // [64][68]   g0^T[d][i] (later y^T[d][i])
    float* sVC = sm + SVC_OFF;   // [64][68]   vc[i][d]
    float* sW1s = sm + SVEC_OFF;          // 128
    float* sW2s = sW1s + 128;             // 64
    float* sKm  = sW2s + 64;              // 64
    float* sXm  = sKm + 64;               // 128
    float* sMd  = sXm + 128;              // 64
    float* sSd  = sMd + 64;               // 64
    float* sLr  = sSd + 64;               // 64
    float* sMp  = sLr + 64;               // 1

    const int t = threadIdx.x;
    const int bh = blockIdx.x;
    const int b = bh >> 4, h = bh & 15;
    const float* qp = g_proc + 0 * NPROC + (size_t)bh * LL * DD;
    const float* kp = g_proc + 1 * NPROC + (size_t)bh * LL * DD;
    const float* vp = g_proc + 2 * NPROC + (size_t)bh * LL * DD;
    const float* gmd = g_gate + 0 * NGATE + (size_t)bh * LL;
    const float* gsd = g_gate + 1 * NGATE + (size_t)bh * LL;
    const float* glr = g_gate + 2 * NGATE + (size_t)bh * LL;

    // init W1, W2, momenta
    for (int e = t; e < DD * DMM; e += 256) {
        int d = e >> 7, c = e & 127;
        sW1[d * 132 + c] = W1g[(size_t)h * DD * DMM + e];
    }
    for (int e = t; e < DMM * DD; e += 256) {
        int c = e >> 6, d = e & 63;
        sW2[c * 68 + d] = W2g[(size_t)h * DMM * DD + e];
    }
    if (t < 128) { sW1s[t] = 0.0f; sXm[t] = 0.0f; }
    if (t < 64)  { sW2s[t] = 0.0f; sKm[t] = 0.0f; }
    __syncthreads();

    const int ty4 = (t >> 4) * 4;
    const int tx8 = (t & 15) * 8;
    const int tx4 = (t & 15) * 4;

    for (int ch = 0; ch < NCH; ch++) {
        const int l0 = ch * CSZ;

        // --- A: load kc^T, vc, gates ---
        for (int e = t; e < CSZ * DD; e += 256) {
            int i = e >> 6, d = e & 63;
            sKT[d * 68 + i] = kp[(size_t)(l0 + i) * DD + d];
            sVC[i * 68 + d] = vp[(size_t)(l0 + i) * DD + d];
        }
        if (t < CSZ) { sMd[t] = gmd[l0 + t]; sSd[t] = gsd[l0 + t]; sLr[t] = glr[l0 + t]; }
        __syncthreads();

        // --- B: Z1 = kc @ W1 ; sig, X1 ---
        {
            float acc[4][8] = {};
            for (int k = 0; k < DD; k++) {
                float4 a = *(const float4*)&sKT[k * 68 + ty4];
                float4 b0 = *(const float4*)&sW1[k * 132 + tx8];
                float4 b1 = *(const float4*)&sW1[k * 132 + tx8 + 4];
                float ar[4] = {a.x, a.y, a.z, a.w};
                float br[8] = {b0.x, b0.y, b0.z, b0.w, b1.x, b1.y, b1.z, b1.w};
#pragma unroll
                for (int i = 0; i < 4; i++)
#pragma unroll
                    for (int j = 0; j < 8; j++) acc[i][j] += ar[i] * br[j];
            }
#pragma unroll
            for (int i = 0; i < 4; i++)
#pragma unroll
                for (int j = 0; j < 8; j++) {
                    float z = acc[i][j];
                    float sg = sigmf(z);
                    int idx = (ty4 + i) * 132 + tx8 + j;
                    sZ1[idx] = z; sSG[idx] = sg; sX1[idx] = z * sg;
                }
        }
        __syncthreads();

        // --- C: g0 = X1 @ W2 - vc  -> sGT[d][i] ---
        {
            float acc[4][4] = {};
            for (int k = 0; k < DMM; k++) {
                float a0 = sX1[(ty4 + 0) * 132 + k];
                float a1 = sX1[(ty4 + 1) * 132 + k];
                float a2 = sX1[(ty4 + 2) * 132 + k];
                float a3 = sX1[(ty4 + 3) * 132 + k];
                float4 bq = *(const float4*)&sW2[k * 68 + tx4];
                float br[4] = {bq.x, bq.y, bq.z, bq.w};
#pragma unroll
                for (int j = 0; j < 4; j++) {
                    acc[0][j] += a0 * br[j];
                    acc[1][j] += a1 * br[j];
                    acc[2][j] += a2 * br[j];
                    acc[3][j] += a3 * br[j];
                }
            }
#pragma unroll
            for (int i = 0; i < 4; i++)
#pragma unroll
                for (int j = 0; j < 4; j++)
                    sGT[(tx4 + j) * 68 + (ty4 + i)] = acc[i][j] - sVC[(ty4 + i) * 68 + tx4 + j];
        }
        __syncthreads();

        // --- D: momentum scans (xmom from X1, kmom from kc), mprod ---
        if (t < DMM) {
            float s = sXm[t];
#pragma unroll 8
            for (int tt = 0; tt < CSZ; tt++) s = sMd[tt] * s + sX1[tt * 132 + t];
            sXm[t] = s;
        } else if (t < DMM + DD) {
            int d = t - DMM;
            float s = sKm[d];
#pragma unroll 8
            for (int tt = 0; tt < CSZ; tt++) s = sMd[tt] * s + sKT[d * 68 + tt];
            sKm[d] = s;
        } else if (t == 255) {
            float p = 1.0f;
#pragma unroll 8
            for (int tt = 0; tt < CSZ; tt++) p *= sMd[tt];
            sMp[0] = p;
        }
        __syncthreads();

        // --- E: g_Z1 = -lr * (g0 @ W2^T) * silu_bwd(Z1) -> sX1 ---
        {
            float acc[4][8] = {};
            for (int k = 0; k < DD; k++) {
                float4 a = *(const float4*)&sGT[k * 68 + ty4];
                float ar[4] = {a.x, a.y, a.z, a.w};
                float br[8];
#pragma unroll
                for (int j = 0; j < 8; j++) br[j] = sW2[(tx8 + j) * 68 + k];
#pragma unroll
                for (int i = 0; i < 4; i++)
#pragma unroll
                    for (int j = 0; j < 8; j++) acc[i][j] += ar[i] * br[j];
            }
#pragma unroll
            for (int i = 0; i < 4; i++) {
                float nlr = -sLr[ty4 + i];
#pragma unroll
                for (int j = 0; j < 8; j++) {
                    int idx = (ty4 + i) * 132 + tx8 + j;
                    float z = sZ1[idx], sg = sSG[idx];
                    float sbw = sg * (1.0f + z * (1.0f - sg));
                    sX1[idx] = nlr * acc[i][j] * sbw;
                }
            }
        }
        __syncthreads();

        // --- F: surprise scans (W1s from g_Z1, W2s from -lr*g0) ---
        if (t < DMM) {
            float s = sW1s[t];
#pragma unroll 8
            for (int tt = 0; tt < CSZ; tt++) s = sSd[tt] * s + sX1[tt * 132 + t];
            sW1s[t] = s;
        } else if (t < DMM + DD) {
            int d = t - DMM;
            float s = sW2s[d];
#pragma unroll 8
            for (int tt = 0; tt < CSZ; tt++) s = sSd[tt] * s + (-sLr[tt]) * sGT[d * 68 + tt];
            sW2s[d] = s;
        }
        __syncthreads();

        // --- G: update W1, W2; load qc^T ---
        {
            float mp = sMp[0];
            for (int e = t; e < DD * DMM; e += 256) {
                int d = e >> 7, c = e & 127;
                sW1[d * 132 + c] = mp * sW1[d * 132 + c] + sKm[d] * sW1s[c];
            }
            for (int e = t; e < DMM * DD; e += 256) {
                int c = e >> 6, d = e & 63;
                sW2[c * 68 + d] = mp * sW2[c * 68 + d] + sXm[c] * sW2s[d];
            }
            for (int e = t; e < CSZ * DD; e += 256) {
                int i = e >> 6, d = e & 63;
                sKT[d * 68 + i] = qp[(size_t)(l0 + i) * DD + d];
            }
        }
        __syncthreads();

        // --- H: Zq = qc @ W1n ; silu -> sZ1 ---
        {
            float acc[4][8] = {};
            for (int k = 0; k < DD; k++) {
                float4 a = *(const float4*)&sKT[k * 68 + ty4];
                float4 b0 = *(const float4*)&sW1[k * 132 + tx8];
                float4 b1 = *(const float4*)&sW1[k * 132 + tx8 + 4];
                float ar[4] = {a.x, a.y, a.z, a.w};
                float br[8] = {b0.x, b0.y, b0.z, b0.w, b1.x, b1.y, b1.z, b1.w};
#pragma unroll
                for (int i = 0; i < 4; i++)
#pragma unroll
                    for (int j = 0; j < 8; j++) acc[i][j] += ar[i] * br[j];
            }
#pragma unroll
            for (int i = 0; i < 4; i++)
#pragma unroll
                for (int j = 0; j < 8; j++) {
                    float z = acc[i][j];
                    sZ1[(ty4 + i) * 132 + tx8 + j] = z * sigmf(z);
                }
        }
        __syncthreads();

        // --- I: y = silu(Zq) @ W2n -> sGT (transposed), then coalesced store ---
        {
            float acc[4][4] = {};
            for (int k = 0; k < DMM; k++) {
                float a0 = sZ1[(ty4 + 0) * 132 + k];
                float a1 = sZ1[(ty4 + 1) * 132 + k];
                float a2 = sZ1[(ty4 + 2) * 132 + k];
                float a3 = sZ1[(ty4 + 3) * 132 + k];
                float4 bq = *(const float4*)&sW2[k * 68 + tx4];
                float br[4] = {bq.x, bq.y, bq.z, bq.w};
#pragma unroll
                for (int j = 0; j < 4; j++) {
                    acc[0][j] += a0 * br[j];
                    acc[1][j] += a1 * br[j];
                    acc[2][j] += a2 * br[j];
                    acc[3][j] += a3 * br[j];
                }
            }
#pragma unroll
            for (int i = 0; i < 4; i++)
#pragma unroll
                for (int j = 0; j < 4; j++)
                    sGT[(tx4 + j) * 68 + (ty4 + i)] = acc[i][j];
        }
        __syncthreads();
        // output layout (per reference's raw reshape): out[b][(h*64+d)*L + l]
        for (int e = t; e < CSZ * DD; e += 256) {
            int d = e >> 6, i = e & 63;
            out[(size_t)b * LL * HIDN + ((size_t)(h * DD + d)) * LL + (l0 + i)] = sGT[d * 68 + i];
        }
        __syncthreads();
    }
}

// ---------------- launch ----------------
extern "C" void kernel_launch(void* const* d_in, const int* in_sizes, int n_in,
                              void* d_out, int out_size) {
    (void)in_sizes; (void)n_in; (void)out_size;
    const float* X    = (const float*)d_in[0];
    const float* Wq   = (const float*)d_in[1];
    const float* Wk   = (const float*)d_in[2];
    const float* Wv   = (const float*)d_in[3];
    const float* cqw  = (const float*)d_in[4];
    const float* cqb  = (const float*)d_in[5];
    const float* ckw  = (const float*)d_in[6];
    const float* ckb  = (const float*)d_in[7];
    const float* cvw  = (const float*)d_in[8];
    const float* cvb  = (const float*)d_in[9];
    const float* qnw  = (const float*)d_in[10];
    const float* knw  = (const float*)d_in[11];
    const float* mdw  = (const float*)d_in[12];
    const float* mdb  = (const float*)d_in[13];
    const float* sw   = (const float*)d_in[14];
    const float* sb   = (const float*)d_in[15];
    const float* lw   = (const float*)d_in[16];
    const float* lb   = (const float*)d_in[17];
    const float* W1g  = (const float*)d_in[18];
    const float* W2g  = (const float*)d_in[19];
    float* out = (float*)d_out;

    cudaFuncSetAttribute(k_scan, cudaFuncAttributeMaxDynamicSharedMemorySize, SMEM_BYTES);

    k_qkv<<<dim3(HIDN / 64, MM / 64, 3), 256>>>(X, Wq, Wk, Wv);
    k_gate<<<dim3(MM / 64), 256>>>(X, mdw, mdb, sw, sb, lw, lb);
    k_conv<<<dim3(LL, BB, 3), 256>>>(cqw, cqb, ckw, ckb, cvw, cvb, qnw, knw);
    k_scan<<<dim3(BB * HH), 256, SMEM_BYTES>>>(W1g, W2g, out);
}